// round 1
// baseline (speedup 1.0000x reference)
#include <cuda_runtime.h>
#include <math.h>

// Problem constants (fixed by the dataset)
#define T_TOK 4096              // B*S tokens
#define D_DIM 1024
#define F_DIM 4096
#define E_NUM 8
#define K_TOP 2

// GEMM tiling
#define BM 128
#define BN 128
#define BK 16

// Row capacity: T*K real rows + per-expert padding to BM multiples
#define CAPR (T_TOK * K_TOP + E_NUM * BM)   // 9216
#define ROWTILES (CAPR / BM)                // 72

// ---------------------------------------------------------------------------
// Scratch (static device globals; no runtime allocation)
// ---------------------------------------------------------------------------
__device__ float g_H[(size_t)CAPR * F_DIM];     // hidden activations  (~151 MB)
__device__ float g_Y[(size_t)CAPR * D_DIM];     // per-row expert outputs (~38 MB)
__device__ int   g_rowtok[CAPR];                // row -> token
__device__ int   g_rowpos[T_TOK * K_TOP];       // (token,k) -> row
__device__ float g_tokw[T_TOK * K_TOP];         // (token,k) -> gate weight
__device__ int   g_toke[T_TOK * K_TOP];         // (token,k) -> expert
__device__ int   g_cnt[E_NUM];
__device__ int   g_cursor[E_NUM];
__device__ int   g_poff[E_NUM + 1];             // padded expert row offsets
__device__ int   g_npad;                        // total padded rows in use

// ---------------------------------------------------------------------------
// K0: reset per-launch state (graph replays!)
// ---------------------------------------------------------------------------
__global__ void reset_kernel() {
    int i = threadIdx.x;
    if (i < E_NUM) g_cnt[i] = 0;
}

// ---------------------------------------------------------------------------
// K1: router — one warp per token. logits = x@router_w + b, top-2, renorm.
// renormalized top-2 softmax == 2-way softmax over top-2 logits.
// ---------------------------------------------------------------------------
__global__ void router_kernel(const float* __restrict__ x,
                              const float* __restrict__ rw,
                              const float* __restrict__ rb) {
    int warp = (blockIdx.x * blockDim.x + threadIdx.x) >> 5;
    int lane = threadIdx.x & 31;
    if (warp >= T_TOK) return;

    const float* xr = x + (size_t)warp * D_DIM;
    float acc[E_NUM];
#pragma unroll
    for (int e = 0; e < E_NUM; e++) acc[e] = 0.0f;

    for (int d = lane; d < D_DIM; d += 32) {
        float xv = xr[d];
        const float* w = rw + (size_t)d * E_NUM;
#pragma unroll
        for (int e = 0; e < E_NUM; e++) acc[e] += xv * w[e];
    }
#pragma unroll
    for (int off = 16; off; off >>= 1) {
#pragma unroll
        for (int e = 0; e < E_NUM; e++)
            acc[e] += __shfl_down_sync(0xFFFFFFFFu, acc[e], off);
    }
    if (lane == 0) {
        float l[E_NUM];
#pragma unroll
        for (int e = 0; e < E_NUM; e++) l[e] = acc[e] + rb[e];
        // top-1 (first index on ties, like jax top_k)
        int i0 = 0;
#pragma unroll
        for (int e = 1; e < E_NUM; e++) if (l[e] > l[i0]) i0 = e;
        // top-2
        int i1 = -1;
#pragma unroll
        for (int e = 0; e < E_NUM; e++) {
            if (e == i0) continue;
            if (i1 < 0 || l[e] > l[i1]) i1 = e;
        }
        float w0 = 1.0f / (1.0f + __expf(l[i1] - l[i0]));
        // use accurate expf for safety:
        w0 = 1.0f / (1.0f + expf(l[i1] - l[i0]));
        float w1 = 1.0f - w0;
        g_toke[warp * 2 + 0] = i0;
        g_toke[warp * 2 + 1] = i1;
        g_tokw[warp * 2 + 0] = w0;
        g_tokw[warp * 2 + 1] = w1;
        atomicAdd(&g_cnt[i0], 1);
        atomicAdd(&g_cnt[i1], 1);
    }
}

// ---------------------------------------------------------------------------
// K2: prefix-sum padded offsets, reset cursors, prefill row map with token 0
// (pad rows compute garbage H with weight 0 => never read by combine)
// ---------------------------------------------------------------------------
__global__ void setup_kernel() {
    if (threadIdx.x == 0) {
        int off = 0;
        for (int e = 0; e < E_NUM; e++) {
            g_poff[e] = off;
            g_cursor[e] = off;
            off += ((g_cnt[e] + BM - 1) / BM) * BM;
        }
        g_poff[E_NUM] = off;
        g_npad = off;
    }
    __syncthreads();
    for (int i = threadIdx.x; i < CAPR; i += blockDim.x) g_rowtok[i] = 0;
}

// ---------------------------------------------------------------------------
// K3: scatter tokens into per-expert row ranges
// ---------------------------------------------------------------------------
__global__ void scatter_kernel() {
    int i = blockIdx.x * blockDim.x + threadIdx.x;
    if (i >= T_TOK * K_TOP) return;
    int e = g_toke[i];
    int p = atomicAdd(&g_cursor[e], 1);
    g_rowtok[i >> 1 == (i >> 1) ? p : p] = i >> 1;   // p is the row slot
    g_rowtok[p] = i >> 1;
    g_rowpos[i] = p;
}

// ---------------------------------------------------------------------------
// K4: GEMM1 + bias + exact GELU.  H[p, f] = gelu(X[tok(p)] @ W1[e] + b1[e])
// 128x128 tile, BK=16, 8x8 per thread, 256 threads.
// ---------------------------------------------------------------------------
__global__ void __launch_bounds__(256)
gemm1_kernel(const float* __restrict__ x,
             const float* __restrict__ w1,
             const float* __restrict__ b1) {
    int row0 = blockIdx.y * BM;
    if (row0 >= g_npad) return;
    int e = 0;
    while (row0 >= g_poff[e + 1]) e++;
    int n0 = blockIdx.x * BN;

    __shared__ float As[BK][BM];
    __shared__ float Bs[BK][BN];

    int tid = threadIdx.x;
    // A-load mapping (fixed across k-tiles): two float4 per thread
    int mA0 = tid >> 2;                 // 0..63
    int mA1 = mA0 + 64;                 // 64..127
    int kqA = (tid & 3) << 2;           // 0,4,8,12
    const float* pA0 = x + (size_t)g_rowtok[row0 + mA0] * D_DIM + kqA;
    const float* pA1 = x + (size_t)g_rowtok[row0 + mA1] * D_DIM + kqA;

    const float* w1e = w1 + (size_t)e * D_DIM * F_DIM;
    int kB = tid >> 5;                  // 0..7
    int nqB = (tid & 31) << 2;          // 0..124
    const float* pB = w1e + (size_t)kB * F_DIM + n0 + nqB;

    int tm = (tid >> 4) << 3;
    int tn = (tid & 15) << 3;

    float acc[8][8];
#pragma unroll
    for (int i = 0; i < 8; i++)
#pragma unroll
        for (int j = 0; j < 8; j++) acc[i][j] = 0.0f;

    for (int k0 = 0; k0 < D_DIM; k0 += BK) {
        float4 a0 = *(const float4*)(pA0 + k0);
        float4 a1 = *(const float4*)(pA1 + k0);
        As[kqA + 0][mA0] = a0.x; As[kqA + 1][mA0] = a0.y;
        As[kqA + 2][mA0] = a0.z; As[kqA + 3][mA0] = a0.w;
        As[kqA + 0][mA1] = a1.x; As[kqA + 1][mA1] = a1.y;
        As[kqA + 2][mA1] = a1.z; As[kqA + 3][mA1] = a1.w;
        float4 b0 = *(const float4*)(pB + (size_t)k0 * F_DIM);
        float4 b1v = *(const float4*)(pB + (size_t)(k0 + 8) * F_DIM);
        *(float4*)&Bs[kB][nqB] = b0;
        *(float4*)&Bs[kB + 8][nqB] = b1v;
        __syncthreads();
#pragma unroll
        for (int k = 0; k < BK; k++) {
            float4 av0 = *(float4*)&As[k][tm];
            float4 av1 = *(float4*)&As[k][tm + 4];
            float4 bv0 = *(float4*)&Bs[k][tn];
            float4 bv1 = *(float4*)&Bs[k][tn + 4];
            float a[8] = {av0.x, av0.y, av0.z, av0.w, av1.x, av1.y, av1.z, av1.w};
            float b[8] = {bv0.x, bv0.y, bv0.z, bv0.w, bv1.x, bv1.y, bv1.z, bv1.w};
#pragma unroll
            for (int i = 0; i < 8; i++)
#pragma unroll
                for (int j = 0; j < 8; j++) acc[i][j] = fmaf(a[i], b[j], acc[i][j]);
        }
        __syncthreads();
    }

    const float* b1e = b1 + (size_t)e * F_DIM + n0 + tn;
#pragma unroll
    for (int i = 0; i < 8; i++) {
        size_t rowbase = (size_t)(row0 + tm + i) * F_DIM + n0 + tn;
#pragma unroll
        for (int j = 0; j < 8; j++) {
            float v = acc[i][j] + b1e[j];
            v = 0.5f * v * (1.0f + erff(v * 0.70710678118654752f));
            g_H[rowbase + j] = v;
        }
    }
}

// ---------------------------------------------------------------------------
// K5: GEMM2 + bias.  Y[p, d] = H[p] @ W2[e] + b2[e]
// ---------------------------------------------------------------------------
__global__ void __launch_bounds__(256)
gemm2_kernel(const float* __restrict__ w2,
             const float* __restrict__ b2) {
    int row0 = blockIdx.y * BM;
    if (row0 >= g_npad) return;
    int e = 0;
    while (row0 >= g_poff[e + 1]) e++;
    int n0 = blockIdx.x * BN;

    __shared__ float As[BK][BM];
    __shared__ float Bs[BK][BN];

    int tid = threadIdx.x;
    int mA0 = tid >> 2;
    int mA1 = mA0 + 64;
    int kqA = (tid & 3) << 2;
    const float* pA0 = g_H + (size_t)(row0 + mA0) * F_DIM + kqA;
    const float* pA1 = g_H + (size_t)(row0 + mA1) * F_DIM + kqA;

    const float* w2e = w2 + (size_t)e * F_DIM * D_DIM;
    int kB = tid >> 5;
    int nqB = (tid & 31) << 2;
    const float* pB = w2e + (size_t)kB * D_DIM + n0 + nqB;

    int tm = (tid >> 4) << 3;
    int tn = (tid & 15) << 3;

    float acc[8][8];
#pragma unroll
    for (int i = 0; i < 8; i++)
#pragma unroll
        for (int j = 0; j < 8; j++) acc[i][j] = 0.0f;

    for (int k0 = 0; k0 < F_DIM; k0 += BK) {
        float4 a0 = *(const float4*)(pA0 + k0);
        float4 a1 = *(const float4*)(pA1 + k0);
        As[kqA + 0][mA0] = a0.x; As[kqA + 1][mA0] = a0.y;
        As[kqA + 2][mA0] = a0.z; As[kqA + 3][mA0] = a0.w;
        As[kqA + 0][mA1] = a1.x; As[kqA + 1][mA1] = a1.y;
        As[kqA + 2][mA1] = a1.z; As[kqA + 3][mA1] = a1.w;
        float4 b0 = *(const float4*)(pB + (size_t)k0 * D_DIM);
        float4 b1v = *(const float4*)(pB + (size_t)(k0 + 8) * D_DIM);
        *(float4*)&Bs[kB][nqB] = b0;
        *(float4*)&Bs[kB + 8][nqB] = b1v;
        __syncthreads();
#pragma unroll
        for (int k = 0; k < BK; k++) {
            float4 av0 = *(float4*)&As[k][tm];
            float4 av1 = *(float4*)&As[k][tm + 4];
            float4 bv0 = *(float4*)&Bs[k][tn];
            float4 bv1 = *(float4*)&Bs[k][tn + 4];
            float a[8] = {av0.x, av0.y, av0.z, av0.w, av1.x, av1.y, av1.z, av1.w};
            float b[8] = {bv0.x, bv0.y, bv0.z, bv0.w, bv1.x, bv1.y, bv1.z, bv1.w};
#pragma unroll
            for (int i = 0; i < 8; i++)
#pragma unroll
                for (int j = 0; j < 8; j++) acc[i][j] = fmaf(a[i], b[j], acc[i][j]);
        }
        __syncthreads();
    }

    const float* b2e = b2 + (size_t)e * D_DIM + n0 + tn;
#pragma unroll
    for (int i = 0; i < 8; i++) {
        size_t rowbase = (size_t)(row0 + tm + i) * D_DIM + n0 + tn;
#pragma unroll
        for (int j = 0; j < 8; j++) {
            g_Y[rowbase + j] = acc[i][j] + b2e[j];
        }
    }
}

// ---------------------------------------------------------------------------
// K6: combine.  out[t] = w0*Y[p0] + w1*Y[p1]   (full overwrite; deterministic)
// ---------------------------------------------------------------------------
__global__ void combine_kernel(float* __restrict__ out) {
    int i = blockIdx.x * blockDim.x + threadIdx.x;   // over T*D/4
    if (i >= T_TOK * (D_DIM / 4)) return;
    int t = i >> 8;                 // D/4 = 256 float4 per row
    int c = (i & 255) << 2;
    int p0 = g_rowpos[t * 2 + 0];
    int p1 = g_rowpos[t * 2 + 1];
    float w0 = g_tokw[t * 2 + 0];
    float w1 = g_tokw[t * 2 + 1];
    float4 y0 = *(const float4*)&g_Y[(size_t)p0 * D_DIM + c];
    float4 y1 = *(const float4*)&g_Y[(size_t)p1 * D_DIM + c];
    float4 o;
    o.x = w0 * y0.x + w1 * y1.x;
    o.y = w0 * y0.y + w1 * y1.y;
    o.z = w0 * y0.z + w1 * y1.z;
    o.w = w0 * y0.w + w1 * y1.w;
    *(float4*)&((float*)out)[(size_t)t * D_DIM + c] = o;
}

// ---------------------------------------------------------------------------
// Launch
// ---------------------------------------------------------------------------
extern "C" void kernel_launch(void* const* d_in, const int* in_sizes, int n_in,
                              void* d_out, int out_size) {
    const float* x  = (const float*)d_in[0];
    const float* rw = (const float*)d_in[1];
    const float* rb = (const float*)d_in[2];
    const float* w1 = (const float*)d_in[3];
    const float* b1 = (const float*)d_in[4];
    const float* w2 = (const float*)d_in[5];
    const float* b2 = (const float*)d_in[6];
    float* out = (float*)d_out;

    reset_kernel<<<1, 32>>>();
    router_kernel<<<(T_TOK * 32 + 255) / 256, 256>>>(x, rw, rb);
    setup_kernel<<<1, 256>>>();
    scatter_kernel<<<(T_TOK * K_TOP + 255) / 256, 256>>>();
    gemm1_kernel<<<dim3(F_DIM / BN, ROWTILES), 256>>>(x, w1, b1);
    gemm2_kernel<<<dim3(D_DIM / BN, ROWTILES), 256>>>(w2, b2);
    combine_kernel<<<(T_TOK * (D_DIM / 4) + 255) / 256, 256>>>(out);
}

// round 3
// speedup vs baseline: 2.3415x; 2.3415x over previous
#include <cuda_runtime.h>
#include <cuda_bf16.h>
#include <math.h>
#include <stdint.h>

// ---------------------------------------------------------------------------
// Problem constants
// ---------------------------------------------------------------------------
#define T_TOK 4096
#define D_DIM 1024
#define F_DIM 4096
#define E_NUM 8
#define K_TOP 2

#define BM 128
#define BN 128
#define BK 32
#define NSTAGE 2

#define CAPR (T_TOK * K_TOP + E_NUM * BM)   // 9216
#define ROWTILES (CAPR / BM)                // 72

// SMEM stage layout (bytes, within one stage)
#define A_ROWB 80                            // 32 bf16 = 64B + 16B pad
#define SM_A_HI 0
#define SM_A_LO (BM * A_ROWB)                // 10240
#define SM_B_HI (2 * BM * A_ROWB)            // 20480
#define SM_B_LO (SM_B_HI + BK * 256)         // 28672
#define STAGEB  (SM_B_LO + BK * 256)         // 36864
#define SM_TOTAL (STAGEB * NSTAGE)           // 73728

// ---------------------------------------------------------------------------
// PTX helpers (sm_103-portable: cp.async + ldmatrix + mma.sync HMMA)
// ---------------------------------------------------------------------------
static __device__ __forceinline__ uint32_t smem_u32(const void* p) {
    uint32_t a;
    asm("{ .reg .u64 t; cvta.to.shared.u64 t, %1; cvt.u32.u64 %0, t; }" : "=r"(a) : "l"(p));
    return a;
}

#define CP16(dst, src) \
    asm volatile("cp.async.cg.shared.global [%0], [%1], 16;" :: "r"(dst), "l"(src))
#define CP_COMMIT() asm volatile("cp.async.commit_group;")
#define CP_WAIT1()  asm volatile("cp.async.wait_group 1;")

#define LDSMX4(R, addr) \
    asm volatile("ldmatrix.sync.aligned.m8n8.x4.shared.b16 {%0,%1,%2,%3}, [%4];" \
        : "=r"((R)[0]), "=r"((R)[1]), "=r"((R)[2]), "=r"((R)[3]) : "r"(addr))
#define LDSMX4T(R, addr) \
    asm volatile("ldmatrix.sync.aligned.m8n8.x4.trans.shared.b16 {%0,%1,%2,%3}, [%4];" \
        : "=r"((R)[0]), "=r"((R)[1]), "=r"((R)[2]), "=r"((R)[3]) : "r"(addr))

#define MMA16816(C, A, B) \
    asm volatile("mma.sync.aligned.m16n8k16.row.col.f32.bf16.bf16.f32 " \
        "{%0,%1,%2,%3}, {%4,%5,%6,%7}, {%8,%9}, {%0,%1,%2,%3};" \
        : "+f"((C)[0]), "+f"((C)[1]), "+f"((C)[2]), "+f"((C)[3]) \
        : "r"((A)[0]), "r"((A)[1]), "r"((A)[2]), "r"((A)[3]), "r"((B)[0]), "r"((B)[1]))

static __device__ __forceinline__ uint32_t pack_bf2(__nv_bfloat16 a, __nv_bfloat16 b) {
    return ((uint32_t)__bfloat16_as_ushort(b) << 16) | (uint32_t)__bfloat16_as_ushort(a);
}

// ---------------------------------------------------------------------------
// Scratch (static device globals)
// ---------------------------------------------------------------------------
__device__ __align__(16) __nv_bfloat16 g_xh[(size_t)T_TOK * D_DIM];
__device__ __align__(16) __nv_bfloat16 g_xl[(size_t)T_TOK * D_DIM];
__device__ __align__(16) __nv_bfloat16 g_w1h[(size_t)E_NUM * D_DIM * F_DIM];
__device__ __align__(16) __nv_bfloat16 g_w1l[(size_t)E_NUM * D_DIM * F_DIM];
__device__ __align__(16) __nv_bfloat16 g_w2h[(size_t)E_NUM * F_DIM * D_DIM];
__device__ __align__(16) __nv_bfloat16 g_w2l[(size_t)E_NUM * F_DIM * D_DIM];
__device__ __align__(16) __nv_bfloat16 g_Hh[(size_t)CAPR * F_DIM];
__device__ __align__(16) __nv_bfloat16 g_Hl[(size_t)CAPR * F_DIM];
__device__ __align__(16) float g_Y[(size_t)CAPR * D_DIM];
__device__ int   g_rowtok[CAPR];
__device__ int   g_rowpos[T_TOK * K_TOP];
__device__ float g_tokw[T_TOK * K_TOP];
__device__ int   g_toke[T_TOK * K_TOP];
__device__ int   g_cnt[E_NUM];
__device__ int   g_cursor[E_NUM];
__device__ int   g_poff[E_NUM + 1];
__device__ int   g_npad;

// ---------------------------------------------------------------------------
// Routing kernels
// ---------------------------------------------------------------------------
__global__ void reset_kernel() {
    if (threadIdx.x < E_NUM) g_cnt[threadIdx.x] = 0;
}

__global__ void router_kernel(const float* __restrict__ x,
                              const float* __restrict__ rw,
                              const float* __restrict__ rb) {
    int warp = (blockIdx.x * blockDim.x + threadIdx.x) >> 5;
    int lane = threadIdx.x & 31;
    if (warp >= T_TOK) return;
    const float* xr = x + (size_t)warp * D_DIM;
    float acc[E_NUM];
#pragma unroll
    for (int e = 0; e < E_NUM; e++) acc[e] = 0.0f;
    for (int d = lane; d < D_DIM; d += 32) {
        float xv = xr[d];
        const float* w = rw + (size_t)d * E_NUM;
#pragma unroll
        for (int e = 0; e < E_NUM; e++) acc[e] += xv * w[e];
    }
#pragma unroll
    for (int off = 16; off; off >>= 1)
#pragma unroll
        for (int e = 0; e < E_NUM; e++)
            acc[e] += __shfl_down_sync(0xFFFFFFFFu, acc[e], off);
    if (lane == 0) {
        float l[E_NUM];
#pragma unroll
        for (int e = 0; e < E_NUM; e++) l[e] = acc[e] + rb[e];
        int i0 = 0;
#pragma unroll
        for (int e = 1; e < E_NUM; e++) if (l[e] > l[i0]) i0 = e;
        int i1 = -1;
#pragma unroll
        for (int e = 0; e < E_NUM; e++) {
            if (e == i0) continue;
            if (i1 < 0 || l[e] > l[i1]) i1 = e;
        }
        float w0 = 1.0f / (1.0f + expf(l[i1] - l[i0]));
        g_toke[warp * 2 + 0] = i0;
        g_toke[warp * 2 + 1] = i1;
        g_tokw[warp * 2 + 0] = w0;
        g_tokw[warp * 2 + 1] = 1.0f - w0;
        atomicAdd(&g_cnt[i0], 1);
        atomicAdd(&g_cnt[i1], 1);
    }
}

__global__ void setup_kernel() {
    if (threadIdx.x == 0) {
        int off = 0;
        for (int e = 0; e < E_NUM; e++) {
            g_poff[e] = off;
            g_cursor[e] = off;
            off += ((g_cnt[e] + BM - 1) / BM) * BM;
        }
        g_poff[E_NUM] = off;
        g_npad = off;
    }
    __syncthreads();
    for (int i = threadIdx.x; i < CAPR; i += blockDim.x) g_rowtok[i] = 0;
}

__global__ void scatter_kernel() {
    int i = blockIdx.x * blockDim.x + threadIdx.x;
    if (i >= T_TOK * K_TOP) return;
    int e = g_toke[i];
    int p = atomicAdd(&g_cursor[e], 1);
    g_rowtok[p] = i >> 1;
    g_rowpos[i] = p;
}

// ---------------------------------------------------------------------------
// Elementwise fp32 -> bf16 hi/lo split.  which: 0=x, 1=w1, 2=w2
// ---------------------------------------------------------------------------
__global__ void split_kernel(const float4* __restrict__ in, int which, int n4) {
    int i = blockIdx.x * blockDim.x + threadIdx.x;
    if (i >= n4) return;
    __nv_bfloat16* hi;
    __nv_bfloat16* lo;
    if (which == 0)      { hi = g_xh;  lo = g_xl;  }
    else if (which == 1) { hi = g_w1h; lo = g_w1l; }
    else                 { hi = g_w2h; lo = g_w2l; }
    float4 v = in[i];
    float vs[4] = {v.x, v.y, v.z, v.w};
    uint32_t hw[2], lw[2];
#pragma unroll
    for (int p = 0; p < 2; p++) {
        __nv_bfloat16 h0 = __float2bfloat16(vs[2 * p]);
        __nv_bfloat16 h1 = __float2bfloat16(vs[2 * p + 1]);
        __nv_bfloat16 l0 = __float2bfloat16(vs[2 * p] - __bfloat162float(h0));
        __nv_bfloat16 l1 = __float2bfloat16(vs[2 * p + 1] - __bfloat162float(h1));
        hw[p] = pack_bf2(h0, h1);
        lw[p] = pack_bf2(l0, l1);
    }
    ((uint2*)hi)[i] = make_uint2(hw[0], hw[1]);
    ((uint2*)lo)[i] = make_uint2(lw[0], lw[1]);
}

// ---------------------------------------------------------------------------
// Split-bf16 HMMA GEMM.  C[128x128] = A[128xK] @ B[KxN-tile]
//   A = Ahi+Alo (bf16 pair), B = Bhi+Blo; acc += AhiBhi + AhiBlo + AloBhi
// GATHER: A rows gathered from token list (GEMM1) vs direct rows (GEMM2)
// GELU:   epilogue bias+gelu-> split bf16 H   vs   bias -> f32 Y
// ---------------------------------------------------------------------------
template<bool GATHER, bool GELU, int KTOT, int NTOT>
__global__ void __launch_bounds__(256, 1)
moe_gemm(const float* __restrict__ bias) {
    int row0 = blockIdx.y * BM;
    if (row0 >= g_npad) return;
    int e = 0;
    while (row0 >= g_poff[e + 1]) e++;
    int n0 = blockIdx.x * BN;

    extern __shared__ char smem[];
    uint32_t su = smem_u32(smem);

    int tid = threadIdx.x;
    int lane = tid & 31;
    int wid = tid >> 5;
    int warp_m = wid & 1;      // 0..1 -> 64 rows each
    int warp_n = wid >> 1;     // 0..3 -> 32 cols each

    // ---- per-thread cp.async source rows
    const __nv_bfloat16 *ahi_g, *alo_g;
    {
        int r = tid >> 1;
        if (GATHER) {
            int tok = g_rowtok[row0 + r];
            ahi_g = g_xh + (size_t)tok * KTOT;
            alo_g = g_xl + (size_t)tok * KTOT;
        } else {
            ahi_g = g_Hh + (size_t)(row0 + r) * KTOT;
            alo_g = g_Hl + (size_t)(row0 + r) * KTOT;
        }
    }
    const __nv_bfloat16* bhi_g = (GATHER ? g_w1h : g_w2h) + (size_t)e * KTOT * NTOT;
    const __nv_bfloat16* blo_g = (GATHER ? g_w1l : g_w2l) + (size_t)e * KTOT * NTOT;

    // per-thread cp.async dest offsets
    int ar = tid >> 1;
    int ac = (tid & 1) * 2;                        // A 16B-chunk base (0 or 2)
    uint32_t a_dst = su + ar * A_ROWB + ac * 16;
    int bkr = tid >> 3;                            // B k-row 0..31
    int bc = (tid & 7) * 2;                        // B 16B-chunk base
    uint32_t b_dst0 = su + SM_B_HI + bkr * 256 + ((bc * 16) ^ ((bkr & 7) << 4));
    uint32_t b_dst1 = su + SM_B_HI + bkr * 256 + (((bc + 1) * 16) ^ ((bkr & 7) << 4));

    float acc[4][4][4];
#pragma unroll
    for (int mt = 0; mt < 4; mt++)
#pragma unroll
        for (int nt = 0; nt < 4; nt++)
#pragma unroll
            for (int q = 0; q < 4; q++) acc[mt][nt][q] = 0.0f;

    // ldmatrix per-thread invariant offsets
    uint32_t a_lds = (uint32_t)((warp_m * 64 + (lane & 15)) * A_ROWB + ((lane >> 4) * 8) * 2);
    int krow_base = (lane & 7) + ((lane >> 3) & 1) * 8;
    int nb_base = (warp_n * 32 + ((lane >> 4) & 1) * 8) * 2;

    const int NK = KTOT / BK;

    // prologue: stage 0
    {
        const __nv_bfloat16* pa = ahi_g + ac * 8;
        CP16(a_dst, pa); CP16(a_dst + 16, pa + 8);
        const __nv_bfloat16* pl = alo_g + ac * 8;
        CP16(a_dst + SM_A_LO, pl); CP16(a_dst + SM_A_LO + 16, pl + 8);
        const __nv_bfloat16* pb = bhi_g + (size_t)bkr * NTOT + n0 + bc * 8;
        CP16(b_dst0, pb); CP16(b_dst1, pb + 8);
        const __nv_bfloat16* pbl = blo_g + (size_t)bkr * NTOT + n0 + bc * 8;
        CP16(b_dst0 + (SM_B_LO - SM_B_HI), pbl);
        CP16(b_dst1 + (SM_B_LO - SM_B_HI), pbl + 8);
        CP_COMMIT();
    }

    for (int kc = 0; kc < NK; kc++) {
        if (kc + 1 < NK) {
            int k0 = (kc + 1) * BK;
            uint32_t soff = ((kc + 1) & 1) * STAGEB;
            const __nv_bfloat16* pa = ahi_g + k0 + ac * 8;
            CP16(a_dst + soff, pa); CP16(a_dst + soff + 16, pa + 8);
            const __nv_bfloat16* pl = alo_g + k0 + ac * 8;
            CP16(a_dst + soff + SM_A_LO, pl); CP16(a_dst + soff + SM_A_LO + 16, pl + 8);
            const __nv_bfloat16* pb = bhi_g + (size_t)(k0 + bkr) * NTOT + n0 + bc * 8;
            CP16(b_dst0 + soff, pb); CP16(b_dst1 + soff, pb + 8);
            const __nv_bfloat16* pbl = blo_g + (size_t)(k0 + bkr) * NTOT + n0 + bc * 8;
            CP16(b_dst0 + soff + (SM_B_LO - SM_B_HI), pbl);
            CP16(b_dst1 + soff + (SM_B_LO - SM_B_HI), pbl + 8);
        }
        CP_COMMIT();
        CP_WAIT1();
        __syncthreads();

        uint32_t sb = su + (kc & 1) * STAGEB;
#pragma unroll
        for (int ks = 0; ks < 2; ks++) {
            uint32_t a_hi[4][4], a_lo[4][4], b_hi[4][2], b_lo[4][2];
#pragma unroll
            for (int mt = 0; mt < 4; mt++) {
                uint32_t ad = sb + a_lds + (uint32_t)(mt * 16 * A_ROWB + ks * 32);
                LDSMX4(a_hi[mt], ad);
                LDSMX4(a_lo[mt], ad + SM_A_LO);
            }
#pragma unroll
            for (int pt = 0; pt < 2; pt++) {
                int krow = ks * 16 + krow_base;
                int nb = nb_base + pt * 32;
                uint32_t bd = sb + SM_B_HI + krow * 256 + (nb ^ ((krow & 7) << 4));
                uint32_t r[4];
                LDSMX4T(r, bd);
                b_hi[2 * pt][0] = r[0]; b_hi[2 * pt][1] = r[1];
                b_hi[2 * pt + 1][0] = r[2]; b_hi[2 * pt + 1][1] = r[3];
                LDSMX4T(r, bd + (SM_B_LO - SM_B_HI));
                b_lo[2 * pt][0] = r[0]; b_lo[2 * pt][1] = r[1];
                b_lo[2 * pt + 1][0] = r[2]; b_lo[2 * pt + 1][1] = r[3];
            }
            // product 1: Ahi * Bhi
#pragma unroll
            for (int mt = 0; mt < 4; mt++)
#pragma unroll
                for (int nt = 0; nt < 4; nt++)
                    MMA16816(acc[mt][nt], a_hi[mt], b_hi[nt]);
            // product 2: Ahi * Blo
#pragma unroll
            for (int mt = 0; mt < 4; mt++)
#pragma unroll
                for (int nt = 0; nt < 4; nt++)
                    MMA16816(acc[mt][nt], a_hi[mt], b_lo[nt]);
            // product 3: Alo * Bhi
#pragma unroll
            for (int mt = 0; mt < 4; mt++)
#pragma unroll
                for (int nt = 0; nt < 4; nt++)
                    MMA16816(acc[mt][nt], a_lo[mt], b_hi[nt]);
        }
        __syncthreads();
    }

    // ---- epilogue
    int tr = lane >> 2;
    int tc = (lane & 3) * 2;
    const float* be = bias + (size_t)e * NTOT;
#pragma unroll
    for (int nt = 0; nt < 4; nt++) {
        int col = n0 + warp_n * 32 + nt * 8 + tc;
        float bv0 = __ldg(be + col);
        float bv1 = __ldg(be + col + 1);
#pragma unroll
        for (int mt = 0; mt < 4; mt++) {
            int rowa = row0 + warp_m * 64 + mt * 16 + tr;
#pragma unroll
            for (int half = 0; half < 2; half++) {
                int row = rowa + half * 8;
                float v0 = acc[mt][nt][2 * half + 0] + bv0;
                float v1 = acc[mt][nt][2 * half + 1] + bv1;
                if (GELU) {
                    v0 = 0.5f * v0 * (1.0f + erff(v0 * 0.70710678118654752f));
                    v1 = 0.5f * v1 * (1.0f + erff(v1 * 0.70710678118654752f));
                    __nv_bfloat16 h0 = __float2bfloat16(v0);
                    __nv_bfloat16 h1 = __float2bfloat16(v1);
                    __nv_bfloat16 l0 = __float2bfloat16(v0 - __bfloat162float(h0));
                    __nv_bfloat16 l1 = __float2bfloat16(v1 - __bfloat162float(h1));
                    *(uint32_t*)(g_Hh + (size_t)row * F_DIM + col) = pack_bf2(h0, h1);
                    *(uint32_t*)(g_Hl + (size_t)row * F_DIM + col) = pack_bf2(l0, l1);
                } else {
                    float2 o = make_float2(v0, v1);
                    *(float2*)(g_Y + (size_t)row * D_DIM + col) = o;
                }
            }
        }
    }
}

// ---------------------------------------------------------------------------
// Combine
// ---------------------------------------------------------------------------
__global__ void combine_kernel(float* __restrict__ out) {
    int i = blockIdx.x * blockDim.x + threadIdx.x;
    if (i >= T_TOK * (D_DIM / 4)) return;
    int t = i >> 8;
    int c = (i & 255) << 2;
    int p0 = g_rowpos[t * 2 + 0];
    int p1 = g_rowpos[t * 2 + 1];
    float w0 = g_tokw[t * 2 + 0];
    float w1 = g_tokw[t * 2 + 1];
    float4 y0 = *(const float4*)&g_Y[(size_t)p0 * D_DIM + c];
    float4 y1 = *(const float4*)&g_Y[(size_t)p1 * D_DIM + c];
    float4 o;
    o.x = w0 * y0.x + w1 * y1.x;
    o.y = w0 * y0.y + w1 * y1.y;
    o.z = w0 * y0.z + w1 * y1.z;
    o.w = w0 * y0.w + w1 * y1.w;
    *(float4*)&((float*)out)[(size_t)t * D_DIM + c] = o;
}

// ---------------------------------------------------------------------------
// Launch
// ---------------------------------------------------------------------------
extern "C" void kernel_launch(void* const* d_in, const int* in_sizes, int n_in,
                              void* d_out, int out_size) {
    const float* x  = (const float*)d_in[0];
    const float* rw = (const float*)d_in[1];
    const float* rb = (const float*)d_in[2];
    const float* w1 = (const float*)d_in[3];
    const float* b1 = (const float*)d_in[4];
    const float* w2 = (const float*)d_in[5];
    const float* b2 = (const float*)d_in[6];
    float* out = (float*)d_out;

    static bool attr_done = false;
    if (!attr_done) {
        cudaFuncSetAttribute(moe_gemm<true, true, D_DIM, F_DIM>,
                             cudaFuncAttributeMaxDynamicSharedMemorySize, SM_TOTAL);
        cudaFuncSetAttribute(moe_gemm<false, false, F_DIM, D_DIM>,
                             cudaFuncAttributeMaxDynamicSharedMemorySize, SM_TOTAL);
        attr_done = true;
    }

    reset_kernel<<<1, 32>>>();
    router_kernel<<<(T_TOK * 32 + 255) / 256, 256>>>(x, rw, rb);
    setup_kernel<<<1, 256>>>();
    scatter_kernel<<<(T_TOK * K_TOP + 255) / 256, 256>>>();

    // bf16 hi/lo splits
    {
        int n4 = T_TOK * D_DIM / 4;
        split_kernel<<<(n4 + 255) / 256, 256>>>((const float4*)x, 0, n4);
    }
    {
        int n4 = E_NUM * D_DIM * F_DIM / 4;
        split_kernel<<<(n4 + 255) / 256, 256>>>((const float4*)w1, 1, n4);
        split_kernel<<<(n4 + 255) / 256, 256>>>((const float4*)w2, 2, n4);
    }

    moe_gemm<true, true, D_DIM, F_DIM>
        <<<dim3(F_DIM / BN, ROWTILES), 256, SM_TOTAL>>>(b1);
    moe_gemm<false, false, F_DIM, D_DIM>
        <<<dim3(D_DIM / BN, ROWTILES), 256, SM_TOTAL>>>(b2);
    combine_kernel<<<(T_TOK * (D_DIM / 4) + 255) / 256, 256>>>(out);
}

// round 4
// speedup vs baseline: 2.4307x; 1.0381x over previous
#include <cuda_runtime.h>
#include <cuda_bf16.h>
#include <math.h>
#include <stdint.h>

// ---------------------------------------------------------------------------
// Problem constants
// ---------------------------------------------------------------------------
#define T_TOK 4096
#define D_DIM 1024
#define F_DIM 4096
#define E_NUM 8
#define K_TOP 2

#define BM 128
#define BN 128
#define BK 32
#define NSTAGE 3

#define CAPR (T_TOK * K_TOP + E_NUM * BM)   // 9216
#define ROWTILES (CAPR / BM)                // 72

// SMEM stage layout (bytes, within one stage)
#define A_ROWB 80                            // 32 bf16 = 64B + 16B pad
#define SM_A_HI 0
#define SM_A_LO (BM * A_ROWB)                // 10240
#define SM_B_HI (2 * BM * A_ROWB)            // 20480
#define SM_B_LO (SM_B_HI + BK * 256)         // 28672
#define STAGEB  (SM_B_LO + BK * 256)         // 36864
#define SM_TOTAL (STAGEB * NSTAGE)           // 110592

// ---------------------------------------------------------------------------
// PTX helpers (sm_103-portable: cp.async + ldmatrix + mma.sync HMMA)
// ---------------------------------------------------------------------------
static __device__ __forceinline__ uint32_t smem_u32(const void* p) {
    uint32_t a;
    asm("{ .reg .u64 t; cvta.to.shared.u64 t, %1; cvt.u32.u64 %0, t; }" : "=r"(a) : "l"(p));
    return a;
}

#define CP16(dst, src) \
    asm volatile("cp.async.cg.shared.global [%0], [%1], 16;" :: "r"(dst), "l"(src))
#define CP_COMMIT() asm volatile("cp.async.commit_group;")
#define CP_WAIT1()  asm volatile("cp.async.wait_group 1;")

#define LDSMX4(R, addr) \
    asm volatile("ldmatrix.sync.aligned.m8n8.x4.shared.b16 {%0,%1,%2,%3}, [%4];" \
        : "=r"((R)[0]), "=r"((R)[1]), "=r"((R)[2]), "=r"((R)[3]) : "r"(addr))
#define LDSMX4T(R, addr) \
    asm volatile("ldmatrix.sync.aligned.m8n8.x4.trans.shared.b16 {%0,%1,%2,%3}, [%4];" \
        : "=r"((R)[0]), "=r"((R)[1]), "=r"((R)[2]), "=r"((R)[3]) : "r"(addr))

#define MMA16816(C, A, B) \
    asm volatile("mma.sync.aligned.m16n8k16.row.col.f32.bf16.bf16.f32 " \
        "{%0,%1,%2,%3}, {%4,%5,%6,%7}, {%8,%9}, {%0,%1,%2,%3};" \
        : "+f"((C)[0]), "+f"((C)[1]), "+f"((C)[2]), "+f"((C)[3]) \
        : "r"((A)[0]), "r"((A)[1]), "r"((A)[2]), "r"((A)[3]), "r"((B)[0]), "r"((B)[1]))

static __device__ __forceinline__ uint32_t pack_bf2(__nv_bfloat16 a, __nv_bfloat16 b) {
    return ((uint32_t)__bfloat16_as_ushort(b) << 16) | (uint32_t)__bfloat16_as_ushort(a);
}

// ---------------------------------------------------------------------------
// Scratch (static device globals)
// ---------------------------------------------------------------------------
__device__ __align__(16) __nv_bfloat16 g_xh[(size_t)T_TOK * D_DIM];
__device__ __align__(16) __nv_bfloat16 g_xl[(size_t)T_TOK * D_DIM];
__device__ __align__(16) __nv_bfloat16 g_w1h[(size_t)E_NUM * D_DIM * F_DIM];
__device__ __align__(16) __nv_bfloat16 g_w1l[(size_t)E_NUM * D_DIM * F_DIM];
__device__ __align__(16) __nv_bfloat16 g_w2h[(size_t)E_NUM * F_DIM * D_DIM];
__device__ __align__(16) __nv_bfloat16 g_w2l[(size_t)E_NUM * F_DIM * D_DIM];
__device__ __align__(16) __nv_bfloat16 g_Hh[(size_t)CAPR * F_DIM];
__device__ __align__(16) __nv_bfloat16 g_Hl[(size_t)CAPR * F_DIM];
__device__ __align__(16) float g_Y[(size_t)CAPR * D_DIM];
__device__ int   g_rowtok[CAPR];
__device__ int   g_rowpos[T_TOK * K_TOP];
__device__ float g_tokw[T_TOK * K_TOP];
__device__ int   g_toke[T_TOK * K_TOP];
__device__ int   g_cnt[E_NUM];
__device__ int   g_cursor[E_NUM];
__device__ int   g_poff[E_NUM + 1];
__device__ int   g_npad;

// ---------------------------------------------------------------------------
// Routing kernels
// ---------------------------------------------------------------------------
__global__ void reset_kernel() {
    if (threadIdx.x < E_NUM) g_cnt[threadIdx.x] = 0;
}

__global__ void router_kernel(const float* __restrict__ x,
                              const float* __restrict__ rw,
                              const float* __restrict__ rb) {
    int warp = (blockIdx.x * blockDim.x + threadIdx.x) >> 5;
    int lane = threadIdx.x & 31;
    if (warp >= T_TOK) return;
    const float* xr = x + (size_t)warp * D_DIM;
    float acc[E_NUM];
#pragma unroll
    for (int e = 0; e < E_NUM; e++) acc[e] = 0.0f;
    for (int d = lane; d < D_DIM; d += 32) {
        float xv = xr[d];
        const float* w = rw + (size_t)d * E_NUM;
#pragma unroll
        for (int e = 0; e < E_NUM; e++) acc[e] += xv * w[e];
    }
#pragma unroll
    for (int off = 16; off; off >>= 1)
#pragma unroll
        for (int e = 0; e < E_NUM; e++)
            acc[e] += __shfl_down_sync(0xFFFFFFFFu, acc[e], off);
    if (lane == 0) {
        float l[E_NUM];
#pragma unroll
        for (int e = 0; e < E_NUM; e++) l[e] = acc[e] + rb[e];
        int i0 = 0;
#pragma unroll
        for (int e = 1; e < E_NUM; e++) if (l[e] > l[i0]) i0 = e;
        int i1 = -1;
#pragma unroll
        for (int e = 0; e < E_NUM; e++) {
            if (e == i0) continue;
            if (i1 < 0 || l[e] > l[i1]) i1 = e;
        }
        float w0 = 1.0f / (1.0f + expf(l[i1] - l[i0]));
        g_toke[warp * 2 + 0] = i0;
        g_toke[warp * 2 + 1] = i1;
        g_tokw[warp * 2 + 0] = w0;
        g_tokw[warp * 2 + 1] = 1.0f - w0;
        atomicAdd(&g_cnt[i0], 1);
        atomicAdd(&g_cnt[i1], 1);
    }
}

__global__ void setup_kernel() {
    if (threadIdx.x == 0) {
        int off = 0;
        for (int e = 0; e < E_NUM; e++) {
            g_poff[e] = off;
            g_cursor[e] = off;
            off += ((g_cnt[e] + BM - 1) / BM) * BM;
        }
        g_poff[E_NUM] = off;
        g_npad = off;
    }
    __syncthreads();
    for (int i = threadIdx.x; i < CAPR; i += blockDim.x) g_rowtok[i] = 0;
}

__global__ void scatter_kernel() {
    int i = blockIdx.x * blockDim.x + threadIdx.x;
    if (i >= T_TOK * K_TOP) return;
    int e = g_toke[i];
    int p = atomicAdd(&g_cursor[e], 1);
    g_rowtok[p] = i >> 1;
    g_rowpos[i] = p;
}

// ---------------------------------------------------------------------------
// Elementwise fp32 -> bf16 hi/lo split.  which: 0=x, 1=w1, 2=w2
// ---------------------------------------------------------------------------
__global__ void split_kernel(const float4* __restrict__ in, int which, int n4) {
    int i = blockIdx.x * blockDim.x + threadIdx.x;
    if (i >= n4) return;
    __nv_bfloat16* hi;
    __nv_bfloat16* lo;
    if (which == 0)      { hi = g_xh;  lo = g_xl;  }
    else if (which == 1) { hi = g_w1h; lo = g_w1l; }
    else                 { hi = g_w2h; lo = g_w2l; }
    float4 v = in[i];
    float vs[4] = {v.x, v.y, v.z, v.w};
    uint32_t hw[2], lw[2];
#pragma unroll
    for (int p = 0; p < 2; p++) {
        __nv_bfloat16 h0 = __float2bfloat16(vs[2 * p]);
        __nv_bfloat16 h1 = __float2bfloat16(vs[2 * p + 1]);
        __nv_bfloat16 l0 = __float2bfloat16(vs[2 * p] - __bfloat162float(h0));
        __nv_bfloat16 l1 = __float2bfloat16(vs[2 * p + 1] - __bfloat162float(h1));
        hw[p] = pack_bf2(h0, h1);
        lw[p] = pack_bf2(l0, l1);
    }
    ((uint2*)hi)[i] = make_uint2(hw[0], hw[1]);
    ((uint2*)lo)[i] = make_uint2(lw[0], lw[1]);
}

// ---------------------------------------------------------------------------
// Split-bf16 HMMA GEMM, 3-stage cp.async pipeline, one barrier per k-chunk.
// ---------------------------------------------------------------------------
template<bool GATHER, bool GELU, int KTOT, int NTOT>
__global__ void __launch_bounds__(256, 2)
moe_gemm(const float* __restrict__ bias) {
    int row0 = blockIdx.y * BM;
    if (row0 >= g_npad) return;
    int e = 0;
    while (row0 >= g_poff[e + 1]) e++;
    int n0 = blockIdx.x * BN;

    extern __shared__ char smem[];
    uint32_t su = smem_u32(smem);

    int tid = threadIdx.x;
    int lane = tid & 31;
    int wid = tid >> 5;
    int warp_m = wid & 1;      // 0..1 -> 64 rows each
    int warp_n = wid >> 1;     // 0..3 -> 32 cols each

    // ---- per-thread cp.async source rows
    const __nv_bfloat16 *ahi_g, *alo_g;
    {
        int r = tid >> 1;
        if (GATHER) {
            int tok = g_rowtok[row0 + r];
            ahi_g = g_xh + (size_t)tok * KTOT;
            alo_g = g_xl + (size_t)tok * KTOT;
        } else {
            ahi_g = g_Hh + (size_t)(row0 + r) * KTOT;
            alo_g = g_Hl + (size_t)(row0 + r) * KTOT;
        }
    }
    const __nv_bfloat16* bhi_g = (GATHER ? g_w1h : g_w2h) + (size_t)e * KTOT * NTOT;
    const __nv_bfloat16* blo_g = (GATHER ? g_w1l : g_w2l) + (size_t)e * KTOT * NTOT;

    // per-thread cp.async dest offsets
    int ar = tid >> 1;
    int ac = (tid & 1) * 2;                        // A 16B-chunk base (0 or 2)
    uint32_t a_dst = su + ar * A_ROWB + ac * 16;
    int bkr = tid >> 3;                            // B k-row 0..31
    int bc = (tid & 7) * 2;                        // B 16B-chunk base
    uint32_t b_dst0 = su + SM_B_HI + bkr * 256 + ((bc * 16) ^ ((bkr & 7) << 4));
    uint32_t b_dst1 = su + SM_B_HI + bkr * 256 + (((bc + 1) * 16) ^ ((bkr & 7) << 4));

    float acc[4][4][4];
#pragma unroll
    for (int mt = 0; mt < 4; mt++)
#pragma unroll
        for (int nt = 0; nt < 4; nt++)
#pragma unroll
            for (int q = 0; q < 4; q++) acc[mt][nt][q] = 0.0f;

    // ldmatrix per-thread invariant offsets
    uint32_t a_lds = (uint32_t)((warp_m * 64 + (lane & 15)) * A_ROWB + ((lane >> 4) * 8) * 2);
    int krow_base = (lane & 7) + ((lane >> 3) & 1) * 8;
    int nb_base = (warp_n * 32 + ((lane >> 4) & 1) * 8) * 2;

    const int NK = KTOT / BK;

    // copy issuer for k-chunk kc into stage buffer sb_off
#define ISSUE_COPY(kc, sb_off)                                                      \
    do {                                                                            \
        int k0_ = (kc) * BK;                                                        \
        const __nv_bfloat16* pa_ = ahi_g + k0_ + ac * 8;                            \
        CP16((sb_off) + a_dst, pa_); CP16((sb_off) + a_dst + 16, pa_ + 8);          \
        const __nv_bfloat16* pl_ = alo_g + k0_ + ac * 8;                            \
        CP16((sb_off) + a_dst + SM_A_LO, pl_);                                      \
        CP16((sb_off) + a_dst + SM_A_LO + 16, pl_ + 8);                             \
        const __nv_bfloat16* pb_ = bhi_g + (size_t)(k0_ + bkr) * NTOT + n0 + bc * 8;\
        CP16((sb_off) + b_dst0, pb_); CP16((sb_off) + b_dst1, pb_ + 8);             \
        const __nv_bfloat16* pq_ = blo_g + (size_t)(k0_ + bkr) * NTOT + n0 + bc * 8;\
        CP16((sb_off) + b_dst0 + (SM_B_LO - SM_B_HI), pq_);                         \
        CP16((sb_off) + b_dst1 + (SM_B_LO - SM_B_HI), pq_ + 8);                     \
    } while (0)

    // prologue: stages 0, 1
    ISSUE_COPY(0, 0);
    CP_COMMIT();
    ISSUE_COPY(1, STAGEB);
    CP_COMMIT();

    int stage = 0;       // buffer index of k-chunk kc
    int stage_w = 2;     // buffer index to write next
    for (int kc = 0; kc < NK; kc++) {
        CP_WAIT1();          // oldest pending group (stage for kc) complete
        __syncthreads();     // everyone sees it; also: all reads of buffer
                             // (kc-1)%3 are done -> safe to overwrite below
        if (kc + 2 < NK) ISSUE_COPY(kc + 2, (uint32_t)stage_w * STAGEB);
        CP_COMMIT();

        uint32_t sb = su + (uint32_t)stage * STAGEB;
#pragma unroll
        for (int ks = 0; ks < 2; ks++) {
            uint32_t a_hi[4][4], a_lo[4][4], b_hi[4][2], b_lo[4][2];
#pragma unroll
            for (int mt = 0; mt < 4; mt++) {
                uint32_t ad = sb + a_lds + (uint32_t)(mt * 16 * A_ROWB + ks * 32);
                LDSMX4(a_hi[mt], ad);
                LDSMX4(a_lo[mt], ad + SM_A_LO);
            }
#pragma unroll
            for (int pt = 0; pt < 2; pt++) {
                int krow = ks * 16 + krow_base;
                int nb = nb_base + pt * 32;
                uint32_t bd = sb + SM_B_HI + krow * 256 + (nb ^ ((krow & 7) << 4));
                uint32_t r[4];
                LDSMX4T(r, bd);
                b_hi[2 * pt][0] = r[0]; b_hi[2 * pt][1] = r[1];
                b_hi[2 * pt + 1][0] = r[2]; b_hi[2 * pt + 1][1] = r[3];
                LDSMX4T(r, bd + (SM_B_LO - SM_B_HI));
                b_lo[2 * pt][0] = r[0]; b_lo[2 * pt][1] = r[1];
                b_lo[2 * pt + 1][0] = r[2]; b_lo[2 * pt + 1][1] = r[3];
            }
#pragma unroll
            for (int mt = 0; mt < 4; mt++)
#pragma unroll
                for (int nt = 0; nt < 4; nt++)
                    MMA16816(acc[mt][nt], a_hi[mt], b_hi[nt]);
#pragma unroll
            for (int mt = 0; mt < 4; mt++)
#pragma unroll
                for (int nt = 0; nt < 4; nt++)
                    MMA16816(acc[mt][nt], a_hi[mt], b_lo[nt]);
#pragma unroll
            for (int mt = 0; mt < 4; mt++)
#pragma unroll
                for (int nt = 0; nt < 4; nt++)
                    MMA16816(acc[mt][nt], a_lo[mt], b_hi[nt]);
        }
        stage = (stage == 2) ? 0 : stage + 1;
        stage_w = (stage_w == 2) ? 0 : stage_w + 1;
    }
#undef ISSUE_COPY

    // ---- epilogue
    int tr = lane >> 2;
    int tc = (lane & 3) * 2;
    const float* be = bias + (size_t)e * NTOT;
#pragma unroll
    for (int nt = 0; nt < 4; nt++) {
        int col = n0 + warp_n * 32 + nt * 8 + tc;
        float bv0 = __ldg(be + col);
        float bv1 = __ldg(be + col + 1);
#pragma unroll
        for (int mt = 0; mt < 4; mt++) {
            int rowa = row0 + warp_m * 64 + mt * 16 + tr;
#pragma unroll
            for (int half = 0; half < 2; half++) {
                int row = rowa + half * 8;
                float v0 = acc[mt][nt][2 * half + 0] + bv0;
                float v1 = acc[mt][nt][2 * half + 1] + bv1;
                if (GELU) {
                    v0 = 0.5f * v0 * (1.0f + erff(v0 * 0.70710678118654752f));
                    v1 = 0.5f * v1 * (1.0f + erff(v1 * 0.70710678118654752f));
                    __nv_bfloat16 h0 = __float2bfloat16(v0);
                    __nv_bfloat16 h1 = __float2bfloat16(v1);
                    __nv_bfloat16 l0 = __float2bfloat16(v0 - __bfloat162float(h0));
                    __nv_bfloat16 l1 = __float2bfloat16(v1 - __bfloat162float(h1));
                    *(uint32_t*)(g_Hh + (size_t)row * F_DIM + col) = pack_bf2(h0, h1);
                    *(uint32_t*)(g_Hl + (size_t)row * F_DIM + col) = pack_bf2(l0, l1);
                } else {
                    float2 o = make_float2(v0, v1);
                    *(float2*)(g_Y + (size_t)row * D_DIM + col) = o;
                }
            }
        }
    }
}

// ---------------------------------------------------------------------------
// Combine
// ---------------------------------------------------------------------------
__global__ void combine_kernel(float* __restrict__ out) {
    int i = blockIdx.x * blockDim.x + threadIdx.x;
    if (i >= T_TOK * (D_DIM / 4)) return;
    int t = i >> 8;
    int c = (i & 255) << 2;
    int p0 = g_rowpos[t * 2 + 0];
    int p1 = g_rowpos[t * 2 + 1];
    float w0 = g_tokw[t * 2 + 0];
    float w1 = g_tokw[t * 2 + 1];
    float4 y0 = *(const float4*)&g_Y[(size_t)p0 * D_DIM + c];
    float4 y1 = *(const float4*)&g_Y[(size_t)p1 * D_DIM + c];
    float4 o;
    o.x = w0 * y0.x + w1 * y1.x;
    o.y = w0 * y0.y + w1 * y1.y;
    o.z = w0 * y0.z + w1 * y1.z;
    o.w = w0 * y0.w + w1 * y1.w;
    *(float4*)&((float*)out)[(size_t)t * D_DIM + c] = o;
}

// ---------------------------------------------------------------------------
// Launch
// ---------------------------------------------------------------------------
extern "C" void kernel_launch(void* const* d_in, const int* in_sizes, int n_in,
                              void* d_out, int out_size) {
    const float* x  = (const float*)d_in[0];
    const float* rw = (const float*)d_in[1];
    const float* rb = (const float*)d_in[2];
    const float* w1 = (const float*)d_in[3];
    const float* b1 = (const float*)d_in[4];
    const float* w2 = (const float*)d_in[5];
    const float* b2 = (const float*)d_in[6];
    float* out = (float*)d_out;

    static bool attr_done = false;
    if (!attr_done) {
        cudaFuncSetAttribute(moe_gemm<true, true, D_DIM, F_DIM>,
                             cudaFuncAttributeMaxDynamicSharedMemorySize, SM_TOTAL);
        cudaFuncSetAttribute(moe_gemm<false, false, F_DIM, D_DIM>,
                             cudaFuncAttributeMaxDynamicSharedMemorySize, SM_TOTAL);
        attr_done = true;
    }

    reset_kernel<<<1, 32>>>();
    router_kernel<<<(T_TOK * 32 + 255) / 256, 256>>>(x, rw, rb);
    setup_kernel<<<1, 256>>>();
    scatter_kernel<<<(T_TOK * K_TOP + 255) / 256, 256>>>();

    // bf16 hi/lo splits
    {
        int n4 = T_TOK * D_DIM / 4;
        split_kernel<<<(n4 + 255) / 256, 256>>>((const float4*)x, 0, n4);
    }
    {
        int n4 = E_NUM * D_DIM * F_DIM / 4;
        split_kernel<<<(n4 + 255) / 256, 256>>>((const float4*)w1, 1, n4);
        split_kernel<<<(n4 + 255) / 256, 256>>>((const float4*)w2, 2, n4);
    }

    moe_gemm<true, true, D_DIM, F_DIM>
        <<<dim3(F_DIM / BN, ROWTILES), 256, SM_TOTAL>>>(b1);
    moe_gemm<false, false, F_DIM, D_DIM>
        <<<dim3(D_DIM / BN, ROWTILES), 256, SM_TOTAL>>>(b2);
    combine_kernel<<<(T_TOK * (D_DIM / 4) + 255) / 256, 256>>>(out);
}

// round 5
// speedup vs baseline: 3.3406x; 1.3743x over previous
#include <cuda_runtime.h>
#include <cuda_fp16.h>
#include <math.h>
#include <stdint.h>

// ---------------------------------------------------------------------------
// Problem constants
// ---------------------------------------------------------------------------
#define T_TOK 4096
#define D_DIM 1024
#define F_DIM 4096
#define E_NUM 8
#define K_TOP 2

#define BM 128
#define BN 128
#define BK 32
#define NSTAGE 3

#define CAPR (T_TOK * K_TOP + E_NUM * BM)   // 9216
#define ROWTILES (CAPR / BM)                // 72

// SMEM stage layout (bytes, within one stage)
#define A_ROWB 80                            // 32 fp16 = 64B + 16B pad
#define SM_A_HI 0
#define SM_A_LO (BM * A_ROWB)                // 10240
#define SM_B    (2 * BM * A_ROWB)            // 20480
#define STAGEB  (SM_B + BK * 256)            // 28672
#define SM_TOTAL (STAGEB * NSTAGE)           // 86016

// ---------------------------------------------------------------------------
// PTX helpers (sm_103-portable: cp.async + ldmatrix + mma.sync HMMA)
// ---------------------------------------------------------------------------
static __device__ __forceinline__ uint32_t smem_u32(const void* p) {
    uint32_t a;
    asm("{ .reg .u64 t; cvta.to.shared.u64 t, %1; cvt.u32.u64 %0, t; }" : "=r"(a) : "l"(p));
    return a;
}

#define CP16(dst, src) \
    asm volatile("cp.async.cg.shared.global [%0], [%1], 16;" :: "r"(dst), "l"(src))
#define CP_COMMIT() asm volatile("cp.async.commit_group;")
#define CP_WAIT1()  asm volatile("cp.async.wait_group 1;")

#define LDSMX4(R, addr) \
    asm volatile("ldmatrix.sync.aligned.m8n8.x4.shared.b16 {%0,%1,%2,%3}, [%4];" \
        : "=r"((R)[0]), "=r"((R)[1]), "=r"((R)[2]), "=r"((R)[3]) : "r"(addr))
#define LDSMX4T(R, addr) \
    asm volatile("ldmatrix.sync.aligned.m8n8.x4.trans.shared.b16 {%0,%1,%2,%3}, [%4];" \
        : "=r"((R)[0]), "=r"((R)[1]), "=r"((R)[2]), "=r"((R)[3]) : "r"(addr))

#define MMA16816(C, A, B) \
    asm volatile("mma.sync.aligned.m16n8k16.row.col.f32.f16.f16.f32 " \
        "{%0,%1,%2,%3}, {%4,%5,%6,%7}, {%8,%9}, {%0,%1,%2,%3};" \
        : "+f"((C)[0]), "+f"((C)[1]), "+f"((C)[2]), "+f"((C)[3]) \
        : "r"((A)[0]), "r"((A)[1]), "r"((A)[2]), "r"((A)[3]), "r"((B)[0]), "r"((B)[1]))

static __device__ __forceinline__ uint32_t pack_h2(__half a, __half b) {
    return ((uint32_t)__half_as_ushort(b) << 16) | (uint32_t)__half_as_ushort(a);
}

// ---------------------------------------------------------------------------
// Scratch (static device globals)
// ---------------------------------------------------------------------------
__device__ __align__(16) __half g_xh[(size_t)T_TOK * D_DIM];
__device__ __align__(16) __half g_xl[(size_t)T_TOK * D_DIM];
__device__ __align__(16) __half g_w1f[(size_t)E_NUM * D_DIM * F_DIM];
__device__ __align__(16) __half g_w2f[(size_t)E_NUM * F_DIM * D_DIM];
__device__ __align__(16) __half g_Hh[(size_t)CAPR * F_DIM];
__device__ __align__(16) __half g_Hl[(size_t)CAPR * F_DIM];
__device__ __align__(16) float g_Y[(size_t)CAPR * D_DIM];
__device__ int   g_rowtok[CAPR];
__device__ int   g_rowpos[T_TOK * K_TOP];
__device__ float g_tokw[T_TOK * K_TOP];
__device__ int   g_toke[T_TOK * K_TOP];
__device__ int   g_cnt[E_NUM];
__device__ int   g_cursor[E_NUM];
__device__ int   g_poff[E_NUM + 1];
__device__ int   g_npad;

// ---------------------------------------------------------------------------
// Routing kernels
// ---------------------------------------------------------------------------
__global__ void reset_kernel() {
    if (threadIdx.x < E_NUM) g_cnt[threadIdx.x] = 0;
}

__global__ void router_kernel(const float* __restrict__ x,
                              const float* __restrict__ rw,
                              const float* __restrict__ rb) {
    int warp = (blockIdx.x * blockDim.x + threadIdx.x) >> 5;
    int lane = threadIdx.x & 31;
    if (warp >= T_TOK) return;
    const float* xr = x + (size_t)warp * D_DIM;
    float acc[E_NUM];
#pragma unroll
    for (int e = 0; e < E_NUM; e++) acc[e] = 0.0f;
    for (int d = lane; d < D_DIM; d += 32) {
        float xv = xr[d];
        const float* w = rw + (size_t)d * E_NUM;
#pragma unroll
        for (int e = 0; e < E_NUM; e++) acc[e] += xv * w[e];
    }
#pragma unroll
    for (int off = 16; off; off >>= 1)
#pragma unroll
        for (int e = 0; e < E_NUM; e++)
            acc[e] += __shfl_down_sync(0xFFFFFFFFu, acc[e], off);
    if (lane == 0) {
        float l[E_NUM];
#pragma unroll
        for (int e = 0; e < E_NUM; e++) l[e] = acc[e] + rb[e];
        int i0 = 0;
#pragma unroll
        for (int e = 1; e < E_NUM; e++) if (l[e] > l[i0]) i0 = e;
        int i1 = -1;
#pragma unroll
        for (int e = 0; e < E_NUM; e++) {
            if (e == i0) continue;
            if (i1 < 0 || l[e] > l[i1]) i1 = e;
        }
        float w0 = 1.0f / (1.0f + expf(l[i1] - l[i0]));
        g_toke[warp * 2 + 0] = i0;
        g_toke[warp * 2 + 1] = i1;
        g_tokw[warp * 2 + 0] = w0;
        g_tokw[warp * 2 + 1] = 1.0f - w0;
        atomicAdd(&g_cnt[i0], 1);
        atomicAdd(&g_cnt[i1], 1);
    }
}

__global__ void setup_kernel() {
    if (threadIdx.x == 0) {
        int off = 0;
        for (int e = 0; e < E_NUM; e++) {
            g_poff[e] = off;
            g_cursor[e] = off;
            off += ((g_cnt[e] + BM - 1) / BM) * BM;
        }
        g_poff[E_NUM] = off;
        g_npad = off;
    }
    __syncthreads();
    for (int i = threadIdx.x; i < CAPR; i += blockDim.x) g_rowtok[i] = 0;
}

__global__ void scatter_kernel() {
    int i = blockIdx.x * blockDim.x + threadIdx.x;
    if (i >= T_TOK * K_TOP) return;
    int e = g_toke[i];
    int p = atomicAdd(&g_cursor[e], 1);
    g_rowtok[p] = i >> 1;
    g_rowpos[i] = p;
}

// ---------------------------------------------------------------------------
// x: fp32 -> fp16 hi + lo split
// ---------------------------------------------------------------------------
__global__ void splitx_kernel(const float4* __restrict__ in, int n4) {
    int i = blockIdx.x * blockDim.x + threadIdx.x;
    if (i >= n4) return;
    float4 v = in[i];
    float vs[4] = {v.x, v.y, v.z, v.w};
    uint32_t hw[2], lw[2];
#pragma unroll
    for (int p = 0; p < 2; p++) {
        __half h0 = __float2half_rn(vs[2 * p]);
        __half h1 = __float2half_rn(vs[2 * p + 1]);
        __half l0 = __float2half_rn(vs[2 * p] - __half2float(h0));
        __half l1 = __float2half_rn(vs[2 * p + 1] - __half2float(h1));
        hw[p] = pack_h2(h0, h1);
        lw[p] = pack_h2(l0, l1);
    }
    ((uint2*)g_xh)[i] = make_uint2(hw[0], hw[1]);
    ((uint2*)g_xl)[i] = make_uint2(lw[0], lw[1]);
}

// weights: fp32 -> fp16 (single)
__global__ void convw_kernel(const float4* __restrict__ in, __half* __restrict__ out, int n4) {
    int i = blockIdx.x * blockDim.x + threadIdx.x;
    if (i >= n4) return;
    float4 v = in[i];
    uint32_t w0 = pack_h2(__float2half_rn(v.x), __float2half_rn(v.y));
    uint32_t w1 = pack_h2(__float2half_rn(v.z), __float2half_rn(v.w));
    ((uint2*)out)[i] = make_uint2(w0, w1);
}

// ---------------------------------------------------------------------------
// Split-fp16 HMMA GEMM: acc += Ahi*B + Alo*B  (2 products)
// 3-stage cp.async pipeline, one barrier per k-chunk.
// ---------------------------------------------------------------------------
template<bool GATHER, bool GELU, int KTOT, int NTOT>
__global__ void __launch_bounds__(256, 2)
moe_gemm(const float* __restrict__ bias) {
    int row0 = blockIdx.y * BM;
    if (row0 >= g_npad) return;
    int e = 0;
    while (row0 >= g_poff[e + 1]) e++;
    int n0 = blockIdx.x * BN;

    extern __shared__ char smem[];
    uint32_t su = smem_u32(smem);

    int tid = threadIdx.x;
    int lane = tid & 31;
    int wid = tid >> 5;
    int warp_m = wid & 1;      // 0..1 -> 64 rows each
    int warp_n = wid >> 1;     // 0..3 -> 32 cols each

    // ---- per-thread cp.async source rows
    const __half *ahi_g, *alo_g;
    {
        int r = tid >> 1;
        if (GATHER) {
            int tok = g_rowtok[row0 + r];
            ahi_g = g_xh + (size_t)tok * KTOT;
            alo_g = g_xl + (size_t)tok * KTOT;
        } else {
            ahi_g = g_Hh + (size_t)(row0 + r) * KTOT;
            alo_g = g_Hl + (size_t)(row0 + r) * KTOT;
        }
    }
    const __half* b_g = (GATHER ? g_w1f : g_w2f) + (size_t)e * KTOT * NTOT;

    // per-thread cp.async dest offsets
    int ar = tid >> 1;
    int ac = (tid & 1) * 2;                        // A 16B-chunk base (0 or 2)
    uint32_t a_dst = su + ar * A_ROWB + ac * 16;
    int bkr = tid >> 3;                            // B k-row 0..31
    int bc = (tid & 7) * 2;                        // B 16B-chunk base
    uint32_t b_dst0 = su + SM_B + bkr * 256 + ((bc * 16) ^ ((bkr & 7) << 4));
    uint32_t b_dst1 = su + SM_B + bkr * 256 + (((bc + 1) * 16) ^ ((bkr & 7) << 4));

    float acc[4][4][4];
#pragma unroll
    for (int mt = 0; mt < 4; mt++)
#pragma unroll
        for (int nt = 0; nt < 4; nt++)
#pragma unroll
            for (int q = 0; q < 4; q++) acc[mt][nt][q] = 0.0f;

    // ldmatrix per-thread invariant offsets
    uint32_t a_lds = (uint32_t)((warp_m * 64 + (lane & 15)) * A_ROWB + ((lane >> 4) * 8) * 2);
    int krow_base = (lane & 7) + ((lane >> 3) & 1) * 8;
    int nb_base = (warp_n * 32 + ((lane >> 4) & 1) * 8) * 2;

    const int NK = KTOT / BK;

    // copy issuer for k-chunk kc into stage buffer at byte offset sb_off
#define ISSUE_COPY(kc, sb_off)                                                      \
    do {                                                                            \
        int k0_ = (kc) * BK;                                                        \
        const __half* pa_ = ahi_g + k0_ + ac * 8;                                   \
        CP16((sb_off) + a_dst, pa_); CP16((sb_off) + a_dst + 16, pa_ + 8);          \
        const __half* pl_ = alo_g + k0_ + ac * 8;                                   \
        CP16((sb_off) + a_dst + SM_A_LO, pl_);                                      \
        CP16((sb_off) + a_dst + SM_A_LO + 16, pl_ + 8);                             \
        const __half* pb_ = b_g + (size_t)(k0_ + bkr) * NTOT + n0 + bc * 8;         \
        CP16((sb_off) + b_dst0, pb_); CP16((sb_off) + b_dst1, pb_ + 8);             \
    } while (0)

    // prologue: stages 0, 1
    ISSUE_COPY(0, 0);
    CP_COMMIT();
    ISSUE_COPY(1, STAGEB);
    CP_COMMIT();

    int stage = 0;       // buffer index of k-chunk kc
    int stage_w = 2;     // buffer index to write next
    for (int kc = 0; kc < NK; kc++) {
        CP_WAIT1();          // oldest pending group (stage for kc) complete
        __syncthreads();     // all reads of buffer (kc-1)%3 done -> safe to fill
        if (kc + 2 < NK) ISSUE_COPY(kc + 2, (uint32_t)stage_w * STAGEB);
        CP_COMMIT();

        uint32_t sb = su + (uint32_t)stage * STAGEB;
#pragma unroll
        for (int ks = 0; ks < 2; ks++) {
            uint32_t a_hi[4][4], a_lo[4][4], b_r[4][2];
#pragma unroll
            for (int mt = 0; mt < 4; mt++) {
                uint32_t ad = sb + a_lds + (uint32_t)(mt * 16 * A_ROWB + ks * 32);
                LDSMX4(a_hi[mt], ad);
                LDSMX4(a_lo[mt], ad + SM_A_LO);
            }
#pragma unroll
            for (int pt = 0; pt < 2; pt++) {
                int krow = ks * 16 + krow_base;
                int nb = nb_base + pt * 32;
                uint32_t bd = sb + SM_B + krow * 256 + (nb ^ ((krow & 7) << 4));
                uint32_t r[4];
                LDSMX4T(r, bd);
                b_r[2 * pt][0] = r[0]; b_r[2 * pt][1] = r[1];
                b_r[2 * pt + 1][0] = r[2]; b_r[2 * pt + 1][1] = r[3];
            }
#pragma unroll
            for (int mt = 0; mt < 4; mt++)
#pragma unroll
                for (int nt = 0; nt < 4; nt++)
                    MMA16816(acc[mt][nt], a_hi[mt], b_r[nt]);
#pragma unroll
            for (int mt = 0; mt < 4; mt++)
#pragma unroll
                for (int nt = 0; nt < 4; nt++)
                    MMA16816(acc[mt][nt], a_lo[mt], b_r[nt]);
        }
        stage = (stage == 2) ? 0 : stage + 1;
        stage_w = (stage_w == 2) ? 0 : stage_w + 1;
    }
#undef ISSUE_COPY

    // ---- epilogue
    int tr = lane >> 2;
    int tc = (lane & 3) * 2;
    const float* be = bias + (size_t)e * NTOT;
#pragma unroll
    for (int nt = 0; nt < 4; nt++) {
        int col = n0 + warp_n * 32 + nt * 8 + tc;
        float bv0 = __ldg(be + col);
        float bv1 = __ldg(be + col + 1);
#pragma unroll
        for (int mt = 0; mt < 4; mt++) {
            int rowa = row0 + warp_m * 64 + mt * 16 + tr;
#pragma unroll
            for (int half = 0; half < 2; half++) {
                int row = rowa + half * 8;
                float v0 = acc[mt][nt][2 * half + 0] + bv0;
                float v1 = acc[mt][nt][2 * half + 1] + bv1;
                if (GELU) {
                    v0 = 0.5f * v0 * (1.0f + erff(v0 * 0.70710678118654752f));
                    v1 = 0.5f * v1 * (1.0f + erff(v1 * 0.70710678118654752f));
                    __half h0 = __float2half_rn(v0);
                    __half h1 = __float2half_rn(v1);
                    __half l0 = __float2half_rn(v0 - __half2float(h0));
                    __half l1 = __float2half_rn(v1 - __half2float(h1));
                    *(uint32_t*)(g_Hh + (size_t)row * F_DIM + col) = pack_h2(h0, h1);
                    *(uint32_t*)(g_Hl + (size_t)row * F_DIM + col) = pack_h2(l0, l1);
                } else {
                    float2 o = make_float2(v0, v1);
                    *(float2*)(g_Y + (size_t)row * D_DIM + col) = o;
                }
            }
        }
    }
}

// ---------------------------------------------------------------------------
// Combine
// ---------------------------------------------------------------------------
__global__ void combine_kernel(float* __restrict__ out) {
    int i = blockIdx.x * blockDim.x + threadIdx.x;
    if (i >= T_TOK * (D_DIM / 4)) return;
    int t = i >> 8;
    int c = (i & 255) << 2;
    int p0 = g_rowpos[t * 2 + 0];
    int p1 = g_rowpos[t * 2 + 1];
    float w0 = g_tokw[t * 2 + 0];
    float w1 = g_tokw[t * 2 + 1];
    float4 y0 = *(const float4*)&g_Y[(size_t)p0 * D_DIM + c];
    float4 y1 = *(const float4*)&g_Y[(size_t)p1 * D_DIM + c];
    float4 o;
    o.x = w0 * y0.x + w1 * y1.x;
    o.y = w0 * y0.y + w1 * y1.y;
    o.z = w0 * y0.z + w1 * y1.z;
    o.w = w0 * y0.w + w1 * y1.w;
    *(float4*)&((float*)out)[(size_t)t * D_DIM + c] = o;
}

// ---------------------------------------------------------------------------
// Launch
// ---------------------------------------------------------------------------
extern "C" void kernel_launch(void* const* d_in, const int* in_sizes, int n_in,
                              void* d_out, int out_size) {
    const float* x  = (const float*)d_in[0];
    const float* rw = (const float*)d_in[1];
    const float* rb = (const float*)d_in[2];
    const float* w1 = (const float*)d_in[3];
    const float* b1 = (const float*)d_in[4];
    const float* w2 = (const float*)d_in[5];
    const float* b2 = (const float*)d_in[6];
    float* out = (float*)d_out;

    static bool attr_done = false;
    if (!attr_done) {
        cudaFuncSetAttribute(moe_gemm<true, true, D_DIM, F_DIM>,
                             cudaFuncAttributeMaxDynamicSharedMemorySize, SM_TOTAL);
        cudaFuncSetAttribute(moe_gemm<false, false, F_DIM, D_DIM>,
                             cudaFuncAttributeMaxDynamicSharedMemorySize, SM_TOTAL);
        attr_done = true;
    }

    reset_kernel<<<1, 32>>>();
    router_kernel<<<(T_TOK * 32 + 255) / 256, 256>>>(x, rw, rb);
    setup_kernel<<<1, 256>>>();
    scatter_kernel<<<(T_TOK * K_TOP + 255) / 256, 256>>>();

    // conversions
    {
        int n4 = T_TOK * D_DIM / 4;
        splitx_kernel<<<(n4 + 255) / 256, 256>>>((const float4*)x, n4);
    }
    {
        __half *w1f, *w2f;
        cudaGetSymbolAddress((void**)&w1f, g_w1f);
        cudaGetSymbolAddress((void**)&w2f, g_w2f);
        int n4 = E_NUM * D_DIM * F_DIM / 4;
        convw_kernel<<<(n4 + 255) / 256, 256>>>((const float4*)w1, w1f, n4);
        convw_kernel<<<(n4 + 255) / 256, 256>>>((const float4*)w2, w2f, n4);
    }

    moe_gemm<true, true, D_DIM, F_DIM>
        <<<dim3(F_DIM / BN, ROWTILES), 256, SM_TOTAL>>>(b1);
    moe_gemm<false, false, F_DIM, D_DIM>
        <<<dim3(D_DIM / BN, ROWTILES), 256, SM_TOTAL>>>(b2);
    combine_kernel<<<(T_TOK * (D_DIM / 4) + 255) / 256, 256>>>(out);
}

// round 6
// speedup vs baseline: 5.3120x; 1.5901x over previous
#include <cuda_runtime.h>
#include <cuda_fp16.h>
#include <math.h>
#include <stdint.h>

// ---------------------------------------------------------------------------
// Problem constants
// ---------------------------------------------------------------------------
#define T_TOK 4096
#define D_DIM 1024
#define F_DIM 4096
#define E_NUM 8
#define K_TOP 2

#define BM 128
#define BN 128
#define BK 32
#define NSTAGE 4

#define CAPR (T_TOK * K_TOP + E_NUM * BM)   // 9216
#define ROWTILES (CAPR / BM)                // 72

// SMEM stage layout (bytes, within one stage)
#define A_ROWB 80                            // 32 fp16 = 64B + 16B pad
#define SM_A    0
#define SM_B    (BM * A_ROWB)                // 10240
#define STAGEB  (SM_B + BK * 256)            // 18432
#define SM_TOTAL (STAGEB * NSTAGE)           // 73728

// ---------------------------------------------------------------------------
// PTX helpers (sm_103-portable: cp.async + ldmatrix + mma.sync HMMA)
// ---------------------------------------------------------------------------
static __device__ __forceinline__ uint32_t smem_u32(const void* p) {
    uint32_t a;
    asm("{ .reg .u64 t; cvta.to.shared.u64 t, %1; cvt.u32.u64 %0, t; }" : "=r"(a) : "l"(p));
    return a;
}

#define CP16(dst, src) \
    asm volatile("cp.async.cg.shared.global [%0], [%1], 16;" :: "r"(dst), "l"(src))
#define CP_COMMIT() asm volatile("cp.async.commit_group;")
#define CP_WAIT2()  asm volatile("cp.async.wait_group 2;")

#define LDSMX4(R, addr) \
    asm volatile("ldmatrix.sync.aligned.m8n8.x4.shared.b16 {%0,%1,%2,%3}, [%4];" \
        : "=r"((R)[0]), "=r"((R)[1]), "=r"((R)[2]), "=r"((R)[3]) : "r"(addr))
#define LDSMX4T(R, addr) \
    asm volatile("ldmatrix.sync.aligned.m8n8.x4.trans.shared.b16 {%0,%1,%2,%3}, [%4];" \
        : "=r"((R)[0]), "=r"((R)[1]), "=r"((R)[2]), "=r"((R)[3]) : "r"(addr))

#define MMA16816(C, A, B) \
    asm volatile("mma.sync.aligned.m16n8k16.row.col.f32.f16.f16.f32 " \
        "{%0,%1,%2,%3}, {%4,%5,%6,%7}, {%8,%9}, {%0,%1,%2,%3};" \
        : "+f"((C)[0]), "+f"((C)[1]), "+f"((C)[2]), "+f"((C)[3]) \
        : "r"((A)[0]), "r"((A)[1]), "r"((A)[2]), "r"((A)[3]), "r"((B)[0]), "r"((B)[1]))

static __device__ __forceinline__ uint32_t pack_h2(__half a, __half b) {
    return ((uint32_t)__half_as_ushort(b) << 16) | (uint32_t)__half_as_ushort(a);
}

// ---------------------------------------------------------------------------
// Scratch (static device globals)
// ---------------------------------------------------------------------------
__device__ __align__(16) __half g_xf[(size_t)T_TOK * D_DIM];
__device__ __align__(16) __half g_w1f[(size_t)E_NUM * D_DIM * F_DIM];
__device__ __align__(16) __half g_w2f[(size_t)E_NUM * F_DIM * D_DIM];
__device__ __align__(16) __half g_Hf[(size_t)CAPR * F_DIM];
__device__ __align__(16) float g_Y[(size_t)CAPR * D_DIM];
__device__ int   g_rowtok[CAPR];
__device__ int   g_rowpos[T_TOK * K_TOP];
__device__ float g_tokw[T_TOK * K_TOP];
__device__ int   g_toke[T_TOK * K_TOP];
__device__ int   g_cnt[E_NUM];
__device__ int   g_cursor[E_NUM];
__device__ int   g_poff[E_NUM + 1];
__device__ int   g_npad;

// ---------------------------------------------------------------------------
// Routing kernels
// ---------------------------------------------------------------------------
__global__ void reset_kernel() {
    if (threadIdx.x < E_NUM) g_cnt[threadIdx.x] = 0;
}

__global__ void router_kernel(const float* __restrict__ x,
                              const float* __restrict__ rw,
                              const float* __restrict__ rb) {
    int warp = (blockIdx.x * blockDim.x + threadIdx.x) >> 5;
    int lane = threadIdx.x & 31;
    if (warp >= T_TOK) return;
    const float* xr = x + (size_t)warp * D_DIM;
    float acc[E_NUM];
#pragma unroll
    for (int e = 0; e < E_NUM; e++) acc[e] = 0.0f;
    for (int d = lane; d < D_DIM; d += 32) {
        float xv = xr[d];
        const float* w = rw + (size_t)d * E_NUM;
#pragma unroll
        for (int e = 0; e < E_NUM; e++) acc[e] += xv * w[e];
    }
#pragma unroll
    for (int off = 16; off; off >>= 1)
#pragma unroll
        for (int e = 0; e < E_NUM; e++)
            acc[e] += __shfl_down_sync(0xFFFFFFFFu, acc[e], off);
    if (lane == 0) {
        float l[E_NUM];
#pragma unroll
        for (int e = 0; e < E_NUM; e++) l[e] = acc[e] + rb[e];
        int i0 = 0;
#pragma unroll
        for (int e = 1; e < E_NUM; e++) if (l[e] > l[i0]) i0 = e;
        int i1 = -1;
#pragma unroll
        for (int e = 0; e < E_NUM; e++) {
            if (e == i0) continue;
            if (i1 < 0 || l[e] > l[i1]) i1 = e;
        }
        float w0 = 1.0f / (1.0f + expf(l[i1] - l[i0]));
        g_toke[warp * 2 + 0] = i0;
        g_toke[warp * 2 + 1] = i1;
        g_tokw[warp * 2 + 0] = w0;
        g_tokw[warp * 2 + 1] = 1.0f - w0;
        atomicAdd(&g_cnt[i0], 1);
        atomicAdd(&g_cnt[i1], 1);
    }
}

__global__ void setup_kernel() {
    if (threadIdx.x == 0) {
        int off = 0;
        for (int e = 0; e < E_NUM; e++) {
            g_poff[e] = off;
            g_cursor[e] = off;
            off += ((g_cnt[e] + BM - 1) / BM) * BM;
        }
        g_poff[E_NUM] = off;
        g_npad = off;
    }
    __syncthreads();
    for (int i = threadIdx.x; i < CAPR; i += blockDim.x) g_rowtok[i] = 0;
}

__global__ void scatter_kernel() {
    int i = blockIdx.x * blockDim.x + threadIdx.x;
    if (i >= T_TOK * K_TOP) return;
    int e = g_toke[i];
    int p = atomicAdd(&g_cursor[e], 1);
    g_rowtok[p] = i >> 1;
    g_rowpos[i] = p;
}

// ---------------------------------------------------------------------------
// fp32 -> fp16 conversion
// ---------------------------------------------------------------------------
__global__ void convh_kernel(const float4* __restrict__ in, __half* __restrict__ out, int n4) {
    int i = blockIdx.x * blockDim.x + threadIdx.x;
    if (i >= n4) return;
    float4 v = in[i];
    uint32_t w0 = pack_h2(__float2half_rn(v.x), __float2half_rn(v.y));
    uint32_t w1 = pack_h2(__float2half_rn(v.z), __float2half_rn(v.w));
    ((uint2*)out)[i] = make_uint2(w0, w1);
}

// ---------------------------------------------------------------------------
// fp16 HMMA GEMM (single product), 4-stage cp.async pipeline,
// one barrier per k-chunk.
// ---------------------------------------------------------------------------
template<bool GATHER, bool GELU, int KTOT, int NTOT>
__global__ void __launch_bounds__(256, 2)
moe_gemm(const float* __restrict__ bias) {
    int row0 = blockIdx.y * BM;
    if (row0 >= g_npad) return;
    int e = 0;
    while (row0 >= g_poff[e + 1]) e++;
    int n0 = blockIdx.x * BN;

    extern __shared__ char smem[];
    uint32_t su = smem_u32(smem);

    int tid = threadIdx.x;
    int lane = tid & 31;
    int wid = tid >> 5;
    int warp_m = wid & 1;      // 0..1 -> 64 rows each
    int warp_n = wid >> 1;     // 0..3 -> 32 cols each

    // ---- per-thread cp.async source rows
    const __half* a_g;
    {
        int r = tid >> 1;
        if (GATHER) {
            int tok = g_rowtok[row0 + r];
            a_g = g_xf + (size_t)tok * KTOT;
        } else {
            a_g = g_Hf + (size_t)(row0 + r) * KTOT;
        }
    }
    const __half* b_g = (GATHER ? g_w1f : g_w2f) + (size_t)e * KTOT * NTOT;

    // per-thread cp.async dest offsets
    int ar = tid >> 1;
    int ac = (tid & 1) * 2;                        // A 16B-chunk base (0 or 2)
    uint32_t a_dst = su + ar * A_ROWB + ac * 16;
    int bkr = tid >> 3;                            // B k-row 0..31
    int bc = (tid & 7) * 2;                        // B 16B-chunk base
    uint32_t b_dst0 = su + SM_B + bkr * 256 + ((bc * 16) ^ ((bkr & 7) << 4));
    uint32_t b_dst1 = su + SM_B + bkr * 256 + (((bc + 1) * 16) ^ ((bkr & 7) << 4));

    float acc[4][4][4];
#pragma unroll
    for (int mt = 0; mt < 4; mt++)
#pragma unroll
        for (int nt = 0; nt < 4; nt++)
#pragma unroll
            for (int q = 0; q < 4; q++) acc[mt][nt][q] = 0.0f;

    // ldmatrix per-thread invariant offsets
    uint32_t a_lds = (uint32_t)((warp_m * 64 + (lane & 15)) * A_ROWB + ((lane >> 4) * 8) * 2);
    int krow_base = (lane & 7) + ((lane >> 3) & 1) * 8;
    int nb_base = (warp_n * 32 + ((lane >> 4) & 1) * 8) * 2;

    const int NK = KTOT / BK;

    // copy issuer for k-chunk kc into stage buffer at byte offset sb_off
#define ISSUE_COPY(kc, sb_off)                                                      \
    do {                                                                            \
        int k0_ = (kc) * BK;                                                        \
        const __half* pa_ = a_g + k0_ + ac * 8;                                     \
        CP16((sb_off) + a_dst, pa_); CP16((sb_off) + a_dst + 16, pa_ + 8);          \
        const __half* pb_ = b_g + (size_t)(k0_ + bkr) * NTOT + n0 + bc * 8;         \
        CP16((sb_off) + b_dst0, pb_); CP16((sb_off) + b_dst1, pb_ + 8);             \
    } while (0)

    // prologue: stages 0, 1, 2
    ISSUE_COPY(0, 0);
    CP_COMMIT();
    ISSUE_COPY(1, STAGEB);
    CP_COMMIT();
    ISSUE_COPY(2, 2 * STAGEB);
    CP_COMMIT();

    int stage = 0;       // buffer index of k-chunk kc
    int stage_w = 3;     // buffer index to write next
    for (int kc = 0; kc < NK; kc++) {
        CP_WAIT2();          // stage for kc complete (<=2 groups pending)
        __syncthreads();     // all reads of buffer (kc-1)%4 done -> safe to fill
        if (kc + 3 < NK) ISSUE_COPY(kc + 3, (uint32_t)stage_w * STAGEB);
        CP_COMMIT();

        uint32_t sb = su + (uint32_t)stage * STAGEB;
#pragma unroll
        for (int ks = 0; ks < 2; ks++) {
            uint32_t a_r[4][4], b_r[4][2];
#pragma unroll
            for (int mt = 0; mt < 4; mt++) {
                uint32_t ad = sb + a_lds + (uint32_t)(mt * 16 * A_ROWB + ks * 32);
                LDSMX4(a_r[mt], ad);
            }
#pragma unroll
            for (int pt = 0; pt < 2; pt++) {
                int krow = ks * 16 + krow_base;
                int nb = nb_base + pt * 32;
                uint32_t bd = sb + SM_B + krow * 256 + (nb ^ ((krow & 7) << 4));
                uint32_t r[4];
                LDSMX4T(r, bd);
                b_r[2 * pt][0] = r[0]; b_r[2 * pt][1] = r[1];
                b_r[2 * pt + 1][0] = r[2]; b_r[2 * pt + 1][1] = r[3];
            }
#pragma unroll
            for (int mt = 0; mt < 4; mt++)
#pragma unroll
                for (int nt = 0; nt < 4; nt++)
                    MMA16816(acc[mt][nt], a_r[mt], b_r[nt]);
        }
        stage = (stage == NSTAGE - 1) ? 0 : stage + 1;
        stage_w = (stage_w == NSTAGE - 1) ? 0 : stage_w + 1;
    }
#undef ISSUE_COPY

    // ---- epilogue
    int tr = lane >> 2;
    int tc = (lane & 3) * 2;
    const float* be = bias + (size_t)e * NTOT;
#pragma unroll
    for (int nt = 0; nt < 4; nt++) {
        int col = n0 + warp_n * 32 + nt * 8 + tc;
        float bv0 = __ldg(be + col);
        float bv1 = __ldg(be + col + 1);
#pragma unroll
        for (int mt = 0; mt < 4; mt++) {
            int rowa = row0 + warp_m * 64 + mt * 16 + tr;
#pragma unroll
            for (int half = 0; half < 2; half++) {
                int row = rowa + half * 8;
                float v0 = acc[mt][nt][2 * half + 0] + bv0;
                float v1 = acc[mt][nt][2 * half + 1] + bv1;
                if (GELU) {
                    v0 = 0.5f * v0 * (1.0f + erff(v0 * 0.70710678118654752f));
                    v1 = 0.5f * v1 * (1.0f + erff(v1 * 0.70710678118654752f));
                    *(uint32_t*)(g_Hf + (size_t)row * F_DIM + col) =
                        pack_h2(__float2half_rn(v0), __float2half_rn(v1));
                } else {
                    float2 o = make_float2(v0, v1);
                    *(float2*)(g_Y + (size_t)row * D_DIM + col) = o;
                }
            }
        }
    }
}

// ---------------------------------------------------------------------------
// Combine
// ---------------------------------------------------------------------------
__global__ void combine_kernel(float* __restrict__ out) {
    int i = blockIdx.x * blockDim.x + threadIdx.x;
    if (i >= T_TOK * (D_DIM / 4)) return;
    int t = i >> 8;
    int c = (i & 255) << 2;
    int p0 = g_rowpos[t * 2 + 0];
    int p1 = g_rowpos[t * 2 + 1];
    float w0 = g_tokw[t * 2 + 0];
    float w1 = g_tokw[t * 2 + 1];
    float4 y0 = *(const float4*)&g_Y[(size_t)p0 * D_DIM + c];
    float4 y1 = *(const float4*)&g_Y[(size_t)p1 * D_DIM + c];
    float4 o;
    o.x = w0 * y0.x + w1 * y1.x;
    o.y = w0 * y0.y + w1 * y1.y;
    o.z = w0 * y0.z + w1 * y1.z;
    o.w = w0 * y0.w + w1 * y1.w;
    *(float4*)&((float*)out)[(size_t)t * D_DIM + c] = o;
}

// ---------------------------------------------------------------------------
// Launch
// ---------------------------------------------------------------------------
extern "C" void kernel_launch(void* const* d_in, const int* in_sizes, int n_in,
                              void* d_out, int out_size) {
    const float* x  = (const float*)d_in[0];
    const float* rw = (const float*)d_in[1];
    const float* rb = (const float*)d_in[2];
    const float* w1 = (const float*)d_in[3];
    const float* b1 = (const float*)d_in[4];
    const float* w2 = (const float*)d_in[5];
    const float* b2 = (const float*)d_in[6];
    float* out = (float*)d_out;

    static bool attr_done = false;
    if (!attr_done) {
        cudaFuncSetAttribute(moe_gemm<true, true, D_DIM, F_DIM>,
                             cudaFuncAttributeMaxDynamicSharedMemorySize, SM_TOTAL);
        cudaFuncSetAttribute(moe_gemm<false, false, F_DIM, D_DIM>,
                             cudaFuncAttributeMaxDynamicSharedMemorySize, SM_TOTAL);
        attr_done = true;
    }

    reset_kernel<<<1, 32>>>();
    router_kernel<<<(T_TOK * 32 + 255) / 256, 256>>>(x, rw, rb);
    setup_kernel<<<1, 256>>>();
    scatter_kernel<<<(T_TOK * K_TOP + 255) / 256, 256>>>();

    // conversions
    {
        __half *xf, *w1f, *w2f;
        cudaGetSymbolAddress((void**)&xf, g_xf);
        cudaGetSymbolAddress((void**)&w1f, g_w1f);
        cudaGetSymbolAddress((void**)&w2f, g_w2f);
        int nx4 = T_TOK * D_DIM / 4;
        convh_kernel<<<(nx4 + 255) / 256, 256>>>((const float4*)x, xf, nx4);
        int n4 = E_NUM * D_DIM * F_DIM / 4;
        convh_kernel<<<(n4 + 255) / 256, 256>>>((const float4*)w1, w1f, n4);
        convh_kernel<<<(n4 + 255) / 256, 256>>>((const float4*)w2, w2f, n4);
    }

    moe_gemm<true, true, D_DIM, F_DIM>
        <<<dim3(F_DIM / BN, ROWTILES), 256, SM_TOTAL>>>(b1);
    moe_gemm<false, false, F_DIM, D_DIM>
        <<<dim3(D_DIM / BN, ROWTILES), 256, SM_TOTAL>>>(b2);
    combine_kernel<<<(T_TOK * (D_DIM / 4) + 255) / 256, 256>>>(out);
}